// round 1
// baseline (speedup 1.0000x reference)
#include <cuda_runtime.h>
#include <math.h>
#include <stdint.h>

#define N_NODES   65536
#define NUM_G     512
#define MAX_N     192
#define DIM       512
#define HEADS     8
#define DH        64
#define KSTRIDE   65   // padded smem stride for K tile (odd -> conflict free)

// ---------------- device scratch (no runtime allocation allowed) ----------------
__device__ float g_KV[(size_t)N_NODES * 1024];   // [node][0:512]=K, [512:1024]=V
__device__ float g_W[1024 * 512];                // concat rows: w_k then w_v
__device__ float g_bKV[1024];                    // concat b_k, b_v
__device__ float g_Wqb[HEADS * 8 * 8 * 64];      // [h][j][hh][o_local]
__device__ float g_pooled[NUM_G * DIM];
__device__ float g_tmp[NUM_G * DIM];
__device__ int   g_counts[NUM_G];
__device__ int   g_offsets[NUM_G];

// ---------------- counts/offsets via binary search (batch_indices sorted) -------
__global__ void counts_kernel(const int* __restrict__ bidx) {
    __shared__ int lb[NUM_G + 1];
    int g = threadIdx.x;
    int lo = 0, hi = N_NODES;
    while (lo < hi) { int mid = (lo + hi) >> 1; if (bidx[mid] < g) lo = mid + 1; else hi = mid; }
    lb[g] = lo;
    if (g == 0) lb[NUM_G] = N_NODES;
    __syncthreads();
    g_offsets[g] = lb[g];
    g_counts[g]  = lb[g + 1] - lb[g];
}

// ---------------- concat w_k/w_v and biases into g_W / g_bKV --------------------
__global__ void concat_kernel(const float* __restrict__ wk, const float* __restrict__ bk,
                              const float* __restrict__ wv, const float* __restrict__ bv) {
    int i = blockIdx.x * 256 + threadIdx.x;   // grid 1024 x 256 = 262144
    g_W[i] = wk[i];
    g_W[262144 + i] = wv[i];
    if (i < 512) { g_bKV[i] = bk[i]; g_bKV[512 + i] = bv[i]; }
}

// ---------------- Wqb[h][j][hh][ol] = sum_r gqf[hh*64+r] * w_q[(h*64+ol)*512 + j*64 + r]
__global__ void __launch_bounds__(512) wqb_kernel(const float* __restrict__ gq,
                                                  const float* __restrict__ wq) {
    int h = blockIdx.x, j = blockIdx.y;
    __shared__ float gqs[512];
    __shared__ float wsh[64 * 65];
    int tid = threadIdx.x;
    gqs[tid] = gq[tid];
    for (int idx = tid; idx < 64 * 64; idx += 512) {
        int row = idx >> 6, cc = idx & 63;
        wsh[row * 65 + cc] = wq[(size_t)(h * 64 + row) * 512 + j * 64 + cc];
    }
    __syncthreads();
    int ol = tid & 63, hh = tid >> 6;
    float v = 0.f;
#pragma unroll 8
    for (int r = 0; r < 64; r++) v += gqs[hh * 64 + r] * wsh[ol * 65 + r];
    g_Wqb[h * 4096 + (j * 8 + hh) * 64 + ol] = v;
}

// ---------------- generic SGEMM: C[M,N] = A[M,K] @ B[N,K]^T + bias, optional relu
template <bool RELU>
__global__ void __launch_bounds__(256) sgemm_bias_kernel(
    const float* __restrict__ A, const float* __restrict__ B,
    const float* __restrict__ bias, float* __restrict__ C,
    int M, int N, int K)
{
    const int BKK = 16;
    __shared__ float As[BKK][128];
    __shared__ float Bs[BKK][128];
    int tid = threadIdx.x;
    int m0 = blockIdx.y * 128;
    int n0 = blockIdx.x * 128;
    int tr = tid >> 4, tc = tid & 15;
    int lr = tid >> 2;
    int lc = (tid & 3) * 4;
    float acc[8][8];
#pragma unroll
    for (int i = 0; i < 8; i++)
#pragma unroll
        for (int j = 0; j < 8; j++) acc[i][j] = 0.f;

    for (int k0 = 0; k0 < K; k0 += BKK) {
#pragma unroll
        for (int p = 0; p < 2; p++) {
            int r = lr + p * 64;
            float4 a = *(const float4*)(A + (size_t)(m0 + r) * K + k0 + lc);
            As[lc + 0][r] = a.x; As[lc + 1][r] = a.y; As[lc + 2][r] = a.z; As[lc + 3][r] = a.w;
            float4 b = *(const float4*)(B + (size_t)(n0 + r) * K + k0 + lc);
            Bs[lc + 0][r] = b.x; Bs[lc + 1][r] = b.y; Bs[lc + 2][r] = b.z; Bs[lc + 3][r] = b.w;
        }
        __syncthreads();
#pragma unroll
        for (int kk = 0; kk < BKK; kk++) {
            float4 a0 = *(const float4*)&As[kk][tr * 8];
            float4 a1 = *(const float4*)&As[kk][tr * 8 + 4];
            float4 b0 = *(const float4*)&Bs[kk][tc * 8];
            float4 b1 = *(const float4*)&Bs[kk][tc * 8 + 4];
            float am[8] = {a0.x, a0.y, a0.z, a0.w, a1.x, a1.y, a1.z, a1.w};
            float bn[8] = {b0.x, b0.y, b0.z, b0.w, b1.x, b1.y, b1.z, b1.w};
#pragma unroll
            for (int i = 0; i < 8; i++)
#pragma unroll
                for (int j = 0; j < 8; j++) acc[i][j] = fmaf(am[i], bn[j], acc[i][j]);
        }
        __syncthreads();
    }
#pragma unroll
    for (int i = 0; i < 8; i++) {
        int m = m0 + tr * 8 + i;
#pragma unroll
        for (int j = 0; j < 8; j++) {
            int n = n0 + tc * 8 + j;
            float v = acc[i][j] + bias[n];
            if (RELU) v = fmaxf(v, 0.f);
            C[(size_t)m * N + n] = v;
        }
    }
}

// ---------------- attention body: templated on NK = ceil(n/32) ------------------
__device__ __forceinline__ float warp_max(float v) {
#pragma unroll
    for (int o = 16; o > 0; o >>= 1) v = fmaxf(v, __shfl_xor_sync(0xffffffffu, v, o));
    return v;
}
__device__ __forceinline__ float warp_sum(float v) {
#pragma unroll
    for (int o = 16; o > 0; o >>= 1) v += __shfl_xor_sync(0xffffffffu, v, o);
    return v;
}

template <int NK>
__device__ void attn_body(int n, int lane, int w,
                          const float* __restrict__ Ksh,
                          const float* __restrict__ Wqb_sh,
                          float* __restrict__ Qw,
                          float* __restrict__ avgw,
                          const unsigned* __restrict__ hpack,
                          float bq0, float bq1)
{
    float aacc[NK];
#pragma unroll
    for (int k = 0; k < NK; k++) aacc[k] = 0.f;

    for (int tb = 0; tb < n; tb += 16) {
        int tvalid = 0;
#pragma unroll
        for (int ii = 0; ii < 4; ii++) {
            int t = tb + 4 * ii + w;
            if (t < n) {
                unsigned hp = hpack[t];
                float q0 = bq0, q1 = bq1;
#pragma unroll
                for (int j = 0; j < 8; j++) {
                    int hh = (hp >> (3 * j)) & 7;
                    const float* wb = &Wqb_sh[(j * 8 + hh) * 64];
                    q0 += wb[lane];
                    q1 += wb[lane + 32];
                }
                Qw[(w * 4 + ii) * 64 + lane] = q0;
                Qw[(w * 4 + ii) * 64 + 32 + lane] = q1;
                tvalid = ii + 1;
            }
        }
        __syncwarp();

        float sc[4][NK];
#pragma unroll
        for (int ii = 0; ii < 4; ii++)
#pragma unroll
            for (int k = 0; k < NK; k++) sc[ii][k] = 0.f;

        for (int c = 0; c < 64; c++) {
            float kv[NK];
#pragma unroll
            for (int k = 0; k < NK; k++) kv[k] = Ksh[(lane + 32 * k) * KSTRIDE + c];
#pragma unroll
            for (int ii = 0; ii < 4; ii++) {
                float q = Qw[(w * 4 + ii) * 64 + c];
#pragma unroll
                for (int k = 0; k < NK; k++) sc[ii][k] = fmaf(q, kv[k], sc[ii][k]);
            }
        }

#pragma unroll
        for (int ii = 0; ii < 4; ii++) {
            if (ii >= tvalid) break;
            float m = -1e30f;
#pragma unroll
            for (int k = 0; k < NK; k++) {
                float v = (lane + 32 * k < n) ? sc[ii][k] * 0.125f : -1e30f;
                sc[ii][k] = v;
                m = fmaxf(m, v);
            }
            m = warp_max(m);
            float lsum = 0.f;
#pragma unroll
            for (int k = 0; k < NK; k++) {
                float e = __expf(sc[ii][k] - m);
                sc[ii][k] = e;
                lsum += e;
            }
            float inv = 1.0f / warp_sum(lsum);
#pragma unroll
            for (int k = 0; k < NK; k++) aacc[k] += sc[ii][k] * inv;
        }
        __syncwarp();
    }
#pragma unroll
    for (int k = 0; k < NK; k++) {
        int s = lane + 32 * k;
        if (s < n) atomicAdd(&avgw[s], aacc[k]);
    }
}

// smem: Ksh 192*65 + Wqb 4096 + Qw 1024 + avgw 192 + hpack 192 = 17984 floats
#define ATT_SMEM (17984 * 4)

__global__ void __launch_bounds__(128) attn_kernel(const float* __restrict__ bq)
{
    int g = blockIdx.x, h = blockIdx.y;
    int ntrue = g_counts[g];
    int off = g_offsets[g];
    extern __shared__ float sm[];
    float* Ksh    = sm;                       // 192*65
    float* Wqb_sh = Ksh + MAX_N * KSTRIDE;    // 4096
    float* Qw     = Wqb_sh + 4096;            // 16*64
    float* avgw   = Qw + 1024;                // 192
    unsigned* hpack = (unsigned*)(avgw + MAX_N);

    int tid = threadIdx.x, lane = tid & 31, w = tid >> 5;

    if (ntrue <= 0) {
        if (tid < 64) g_pooled[g * DIM + h * 64 + tid] = 0.f;
        return;
    }
    int n = ntrue < MAX_N ? ntrue : MAX_N;

    for (int idx = tid; idx < n * 64; idx += 128) {
        int s = idx >> 6, c = idx & 63;
        Ksh[s * KSTRIDE + c] = g_KV[(size_t)(off + s) * 1024 + h * 64 + c];
    }
    for (int idx = tid; idx < 4096; idx += 128) Wqb_sh[idx] = g_Wqb[h * 4096 + idx];
    for (int idx = tid; idx < MAX_N; idx += 128) avgw[idx] = 0.f;
    for (int t = tid; t < n; t += 128) {
        unsigned p = 0;
#pragma unroll
        for (int j = 0; j < 8; j++) {
            unsigned hh = (unsigned)(8 * t + j) / (unsigned)ntrue;
            p |= hh << (3 * j);
        }
        hpack[t] = p;
    }
    __syncthreads();

    float bq0 = bq[h * 64 + lane], bq1 = bq[h * 64 + 32 + lane];
    int nk = (n + 31) >> 5;
    switch (nk) {
        case 1: attn_body<1>(n, lane, w, Ksh, Wqb_sh, Qw, avgw, hpack, bq0, bq1); break;
        case 2: attn_body<2>(n, lane, w, Ksh, Wqb_sh, Qw, avgw, hpack, bq0, bq1); break;
        case 3: attn_body<3>(n, lane, w, Ksh, Wqb_sh, Qw, avgw, hpack, bq0, bq1); break;
        case 4: attn_body<4>(n, lane, w, Ksh, Wqb_sh, Qw, avgw, hpack, bq0, bq1); break;
        case 5: attn_body<5>(n, lane, w, Ksh, Wqb_sh, Qw, avgw, hpack, bq0, bq1); break;
        default: attn_body<6>(n, lane, w, Ksh, Wqb_sh, Qw, avgw, hpack, bq0, bq1); break;
    }
    __syncthreads();

    // epilogue: pooled_pre[g, h*64+c] = (1/ntrue) * sum_s avgw[s] * V[off+s, h*64+c]
    int c = tid & 63, half = tid >> 6;
    float acc = 0.f;
    const float* Vb = &g_KV[(size_t)off * 1024 + 512 + h * 64 + c];
    for (int s = half; s < n; s += 2) acc = fmaf(avgw[s], Vb[(size_t)s * 1024], acc);
    if (half) Qw[c] = acc;
    __syncthreads();
    if (!half) g_pooled[g * DIM + h * 64 + c] = (acc + Qw[c]) / (float)ntrue;
}

// ---------------- host launcher --------------------------------------------------
extern "C" void kernel_launch(void* const* d_in, const int* in_sizes, int n_in,
                              void* d_out, int out_size)
{
    const float* x  = (const float*)d_in[0];
    const int*   bi = (const int*)  d_in[1];
    const float* gq = (const float*)d_in[2];
    const float* wq = (const float*)d_in[3];
    const float* bq = (const float*)d_in[4];
    const float* wk = (const float*)d_in[5];
    const float* bk = (const float*)d_in[6];
    const float* wv = (const float*)d_in[7];
    const float* bv = (const float*)d_in[8];
    const float* wo = (const float*)d_in[9];
    const float* bo = (const float*)d_in[10];
    const float* wp = (const float*)d_in[11];
    const float* bp = (const float*)d_in[12];
    float* out = (float*)d_out;

    void *pKV, *pW, *pbKV, *pPooled, *pTmp;
    cudaGetSymbolAddress(&pKV, g_KV);
    cudaGetSymbolAddress(&pW, g_W);
    cudaGetSymbolAddress(&pbKV, g_bKV);
    cudaGetSymbolAddress(&pPooled, g_pooled);
    cudaGetSymbolAddress(&pTmp, g_tmp);

    cudaFuncSetAttribute(attn_kernel, cudaFuncAttributeMaxDynamicSharedMemorySize, ATT_SMEM);

    concat_kernel<<<1024, 256>>>(wk, bk, wv, bv);
    counts_kernel<<<1, NUM_G>>>(bi);
    wqb_kernel<<<dim3(HEADS, 8), 512>>>(gq, wq);

    // K/V projection: [65536,512] @ [1024,512]^T + bias -> g_KV
    sgemm_bias_kernel<false><<<dim3(8, 512), 256>>>(
        x, (const float*)pW, (const float*)pbKV, (float*)pKV, N_NODES, 1024, DIM);

    attn_kernel<<<dim3(NUM_G, HEADS), 128, ATT_SMEM>>>(bq);

    // pooled @ w_o^T + b_o -> tmp ; relu(tmp @ w_p^T + b_p) -> out
    sgemm_bias_kernel<false><<<dim3(4, 4), 256>>>(
        (const float*)pPooled, wo, bo, (float*)pTmp, NUM_G, DIM, DIM);
    sgemm_bias_kernel<true><<<dim3(4, 4), 256>>>(
        (const float*)pTmp, wp, bp, out, NUM_G, DIM, DIM);
}

// round 3
// speedup vs baseline: 1.6573x; 1.6573x over previous
#include <cuda_runtime.h>
#include <cuda_bf16.h>
#include <math.h>
#include <stdint.h>

#define N_NODES   65536
#define NUM_G     512
#define MAX_N     192
#define DIM       512
#define HEADS     8
#define DH        64
#define KSTRIDE   65

// ---- K/V projection GEMM config (mma.sync bf16, 3-term error compensation) ----
#define BM 128
#define BN 128
#define BK 64            // bf16 per chunk = 128 bytes = one swizzled smem row
#define NCHUNK 24        // 3 passes x 512/64
#define STAGES 3
#define STG_BYTES 32768  // A 16KB + B 16KB
#define GEMM_SMEM (STAGES * STG_BYTES)

// ---------------- device scratch ----------------
__device__ float         g_KV[(size_t)N_NODES * 1024];   // [node][0:512]=K,[512:1024]=V
__device__ __nv_bfloat16 g_Xx[(size_t)N_NODES * 1024];   // [node][0:512]=hi,[512:1024]=lo
__device__ __nv_bfloat16 g_Wx[(size_t)1024 * 1024];      // [ch(wk;wv)][0:512]=hi,[512:1024]=lo
__device__ float         g_bKV[1024];
__device__ float         g_Wqb[HEADS * 8 * 8 * 64];
__device__ float         g_pooled[NUM_G * DIM];
__device__ float         g_tmp[NUM_G * DIM];
__device__ int           g_counts[NUM_G];
__device__ int           g_offsets[NUM_G];

// ---------------- helpers ----------------
__device__ __forceinline__ uint32_t smem_u32(const void* p) {
    uint32_t a;
    asm("{ .reg .u64 t; cvta.to.shared.u64 t, %1; cvt.u32.u64 %0, t; }" : "=r"(a) : "l"(p));
    return a;
}
#define SWZ(b) ((b) ^ (((b) >> 3) & 0x70))

__device__ __forceinline__ void cp_async16(uint32_t dst, const void* src) {
    asm volatile("cp.async.cg.shared.global [%0], [%1], 16;" :: "r"(dst), "l"(src));
}
__device__ __forceinline__ void cp_commit() {
    asm volatile("cp.async.commit_group;" ::: "memory");
}
template <int N> __device__ __forceinline__ void cp_wait() {
    asm volatile("cp.async.wait_group %0;" :: "n"(N) : "memory");
}
__device__ __forceinline__ void ldm_x4(uint32_t& r0, uint32_t& r1, uint32_t& r2, uint32_t& r3,
                                       uint32_t addr) {
    asm volatile("ldmatrix.sync.aligned.m8n8.x4.shared.b16 {%0,%1,%2,%3}, [%4];"
                 : "=r"(r0), "=r"(r1), "=r"(r2), "=r"(r3) : "r"(addr));
}
__device__ __forceinline__ void mma_bf16(float& d0, float& d1, float& d2, float& d3,
                                         uint32_t a0, uint32_t a1, uint32_t a2, uint32_t a3,
                                         uint32_t b0, uint32_t b1) {
    asm volatile("mma.sync.aligned.m16n8k16.row.col.f32.bf16.bf16.f32 "
                 "{%0,%1,%2,%3}, {%4,%5,%6,%7}, {%8,%9}, {%0,%1,%2,%3};"
                 : "+f"(d0), "+f"(d1), "+f"(d2), "+f"(d3)
                 : "r"(a0), "r"(a1), "r"(a2), "r"(a3), "r"(b0), "r"(b1));
}

// ---------------- counts/offsets + bias concat ----------------
__global__ void counts_kernel(const int* __restrict__ bidx,
                              const float* __restrict__ bk, const float* __restrict__ bv) {
    __shared__ int lb[NUM_G + 1];
    int g = threadIdx.x;
    int lo = 0, hi = N_NODES;
    while (lo < hi) { int mid = (lo + hi) >> 1; if (bidx[mid] < g) lo = mid + 1; else hi = mid; }
    lb[g] = lo;
    if (g == 0) lb[NUM_G] = N_NODES;
    __syncthreads();
    g_offsets[g] = lb[g];
    g_counts[g]  = lb[g + 1] - lb[g];
    g_bKV[g] = bk[g];
    g_bKV[512 + g] = bv[g];
}

// ---------------- fp32 -> bf16 hi/lo splits ----------------
__device__ __forceinline__ void split4(float4 v, uint2* hi, uint2* lo) {
    __nv_bfloat16 h0 = __float2bfloat16_rn(v.x), h1 = __float2bfloat16_rn(v.y);
    __nv_bfloat16 h2 = __float2bfloat16_rn(v.z), h3 = __float2bfloat16_rn(v.w);
    __nv_bfloat16 l0 = __float2bfloat16_rn(v.x - __bfloat162float(h0));
    __nv_bfloat16 l1 = __float2bfloat16_rn(v.y - __bfloat162float(h1));
    __nv_bfloat16 l2 = __float2bfloat16_rn(v.z - __bfloat162float(h2));
    __nv_bfloat16 l3 = __float2bfloat16_rn(v.w - __bfloat162float(h3));
    hi->x = (uint32_t)__bfloat16_as_ushort(h0) | ((uint32_t)__bfloat16_as_ushort(h1) << 16);
    hi->y = (uint32_t)__bfloat16_as_ushort(h2) | ((uint32_t)__bfloat16_as_ushort(h3) << 16);
    lo->x = (uint32_t)__bfloat16_as_ushort(l0) | ((uint32_t)__bfloat16_as_ushort(l1) << 16);
    lo->y = (uint32_t)__bfloat16_as_ushort(l2) | ((uint32_t)__bfloat16_as_ushort(l3) << 16);
}

__global__ void __launch_bounds__(256) convx_kernel(const float* __restrict__ x) {
    size_t i = (size_t)blockIdx.x * 256 + threadIdx.x;   // 65536*128 float4 units
    float4 v = ((const float4*)x)[i];
    size_t r = i >> 7;
    int c4 = (int)(i & 127);
    uint2 hi, lo;
    split4(v, &hi, &lo);
    ((uint2*)(g_Xx + r * 1024))[c4]       = hi;
    ((uint2*)(g_Xx + r * 1024 + 512))[c4] = lo;
}

__global__ void __launch_bounds__(256) convw_kernel(const float* __restrict__ wk,
                                                    const float* __restrict__ wv) {
    int i = blockIdx.x * 256 + threadIdx.x;              // 1024*128 float4 units
    int r = i >> 7;
    int c4 = i & 127;
    float4 v = (r < 512) ? ((const float4*)wk)[(size_t)r * 128 + c4]
                         : ((const float4*)wv)[(size_t)(r - 512) * 128 + c4];
    uint2 hi, lo;
    split4(v, &hi, &lo);
    ((uint2*)(g_Wx + (size_t)r * 1024))[c4]       = hi;
    ((uint2*)(g_Wx + (size_t)r * 1024 + 512))[c4] = lo;
}

// ---------------- Wqb precompute ----------------
__global__ void __launch_bounds__(512) wqb_kernel(const float* __restrict__ gq,
                                                  const float* __restrict__ wq) {
    int h = blockIdx.x, j = blockIdx.y;
    __shared__ float gqs[512];
    __shared__ float wsh[64 * 65];
    int tid = threadIdx.x;
    gqs[tid] = gq[tid];
    for (int idx = tid; idx < 64 * 64; idx += 512) {
        int row = idx >> 6, cc = idx & 63;
        wsh[row * 65 + cc] = wq[(size_t)(h * 64 + row) * 512 + j * 64 + cc];
    }
    __syncthreads();
    int ol = tid & 63, hh = tid >> 6;
    float v = 0.f;
#pragma unroll 8
    for (int r = 0; r < 64; r++) v += gqs[hh * 64 + r] * wsh[ol * 65 + r];
    g_Wqb[h * 4096 + (j * 8 + hh) * 64 + ol] = v;
}

// ---------------- bf16 mma.sync K/V GEMM ----------------
// C[node, ch] = sum over 3 compensation terms of Xx * Wx
// chunk c: X col offset kx, W col offset kw:
//   c 0-7 : Whi*Xhi   c 8-15: Wlo*Xhi   c 16-23: Whi*Xlo
__device__ __forceinline__ void gemm_load_chunk(uint32_t sA, uint32_t sB,
                                                int m0, int n0, int c, int tid) {
    int kq = (c & 7) * 64;
    int kx = kq + ((c >= 16) ? 512 : 0);
    int kw = kq + ((c >= 8 && c < 16) ? 512 : 0);
#pragma unroll
    for (int u = 0; u < 4; u++) {
        int idx = tid + u * 256;         // 1024 x 16B = 16KB
        int row = idx >> 3;
        int cb = (idx & 7) * 16;
        cp_async16(sA + SWZ(row * 128 + cb),
                   (const char*)(g_Xx + (size_t)(m0 + row) * 1024 + kx) + cb);
    }
#pragma unroll
    for (int u = 0; u < 4; u++) {
        int idx = tid + u * 256;
        int row = idx >> 3;
        int cb = (idx & 7) * 16;
        cp_async16(sB + SWZ(row * 128 + cb),
                   (const char*)(g_Wx + (size_t)(n0 + row) * 1024 + kw) + cb);
    }
    cp_commit();
}

__global__ void __launch_bounds__(256, 1) kv_gemm_kernel() {
    extern __shared__ char smem[];
    uint32_t sbase = smem_u32(smem);
    int tid = threadIdx.x;
    int lane = tid & 31, w = tid >> 5;
    int wm = w >> 2, wn = w & 3;                 // 2 x 4 warp grid
    int m0 = blockIdx.y * BM;                    // nodes
    int n0 = blockIdx.x * BN;                    // channels

    float acc[4][4][4];
#pragma unroll
    for (int i = 0; i < 4; i++)
#pragma unroll
        for (int j = 0; j < 4; j++)
#pragma unroll
            for (int k = 0; k < 4; k++) acc[i][j][k] = 0.f;

    gemm_load_chunk(sbase, sbase + 16384, m0, n0, 0, tid);
    gemm_load_chunk(sbase + STG_BYTES, sbase + STG_BYTES + 16384, m0, n0, 1, tid);

    // ldmatrix lane addressing (x4): lane l -> matrix l/8, row l%8
    int lrow = ((lane >> 3) & 1) * 8 + (lane & 7);   // row within 16
    int lcol = ((lane >> 4) & 1) * 16;               // 16B col within 32B kstep

    for (int c = 0; c < NCHUNK; c++) {
        if (c < NCHUNK - 1) cp_wait<1>(); else cp_wait<0>();
        __syncthreads();
        if (c + 2 < NCHUNK) {
            uint32_t st = sbase + ((c + 2) % STAGES) * STG_BYTES;
            gemm_load_chunk(st, st + 16384, m0, n0, c + 2, tid);
        }
        uint32_t sA = sbase + (c % STAGES) * STG_BYTES;
        uint32_t sB = sA + 16384;

#pragma unroll
        for (int ks = 0; ks < 4; ks++) {
            uint32_t a[4][4], b[2][4];
#pragma unroll
            for (int mt = 0; mt < 4; mt++) {
                uint32_t addr = sA + SWZ((wm * 64 + mt * 16 + lrow) * 128 + ks * 32 + lcol);
                ldm_x4(a[mt][0], a[mt][1], a[mt][2], a[mt][3], addr);
            }
#pragma unroll
            for (int nt = 0; nt < 2; nt++) {
                uint32_t addr = sB + SWZ((wn * 32 + nt * 16 + lrow) * 128 + ks * 32 + lcol);
                ldm_x4(b[nt][0], b[nt][1], b[nt][2], b[nt][3], addr);
            }
#pragma unroll
            for (int mt = 0; mt < 4; mt++)
#pragma unroll
                for (int nt = 0; nt < 4; nt++) {
                    uint32_t b0 = b[nt >> 1][(nt & 1) ? 1 : 0];
                    uint32_t b1 = b[nt >> 1][(nt & 1) ? 3 : 2];
                    mma_bf16(acc[mt][nt][0], acc[mt][nt][1], acc[mt][nt][2], acc[mt][nt][3],
                             a[mt][0], a[mt][1], a[mt][2], a[mt][3], b0, b1);
                }
        }
        __syncthreads();
    }

    // epilogue: d0,d1 -> (row lane/4, cols 2*(lane%4)+{0,1}); d2,d3 -> row+8
    int mrow = lane >> 2;
    int ncol = (lane & 3) * 2;
#pragma unroll
    for (int mt = 0; mt < 4; mt++) {
#pragma unroll
        for (int nt = 0; nt < 4; nt++) {
            int m = m0 + wm * 64 + mt * 16 + mrow;
            int n = n0 + wn * 32 + nt * 8 + ncol;
            float2 bias = *(const float2*)&g_bKV[n];
            float2 v0 = make_float2(acc[mt][nt][0] + bias.x, acc[mt][nt][1] + bias.y);
            float2 v1 = make_float2(acc[mt][nt][2] + bias.x, acc[mt][nt][3] + bias.y);
            *(float2*)&g_KV[(size_t)m * 1024 + n] = v0;
            *(float2*)&g_KV[(size_t)(m + 8) * 1024 + n] = v1;
        }
    }
}

// ---------------- small SGEMM (output projections) ----------------
template <bool RELU>
__global__ void __launch_bounds__(256) sgemm_bias_kernel(
    const float* __restrict__ A, const float* __restrict__ B,
    const float* __restrict__ bias, float* __restrict__ C,
    int M, int N, int K)
{
    const int BKK = 16;
    __shared__ float As[BKK][128];
    __shared__ float Bs[BKK][128];
    int tid = threadIdx.x;
    int m0 = blockIdx.y * 128;
    int n0 = blockIdx.x * 128;
    int tr = tid >> 4, tc = tid & 15;
    int lr = tid >> 2;
    int lc = (tid & 3) * 4;
    float acc[8][8];
#pragma unroll
    for (int i = 0; i < 8; i++)
#pragma unroll
        for (int j = 0; j < 8; j++) acc[i][j] = 0.f;

    for (int k0 = 0; k0 < K; k0 += BKK) {
#pragma unroll
        for (int p = 0; p < 2; p++) {
            int r = lr + p * 64;
            float4 a = *(const float4*)(A + (size_t)(m0 + r) * K + k0 + lc);
            As[lc + 0][r] = a.x; As[lc + 1][r] = a.y; As[lc + 2][r] = a.z; As[lc + 3][r] = a.w;
            float4 b = *(const float4*)(B + (size_t)(n0 + r) * K + k0 + lc);
            Bs[lc + 0][r] = b.x; Bs[lc + 1][r] = b.y; Bs[lc + 2][r] = b.z; Bs[lc + 3][r] = b.w;
        }
        __syncthreads();
#pragma unroll
        for (int kk = 0; kk < BKK; kk++) {
            float4 a0 = *(const float4*)&As[kk][tr * 8];
            float4 a1 = *(const float4*)&As[kk][tr * 8 + 4];
            float4 b0 = *(const float4*)&Bs[kk][tc * 8];
            float4 b1 = *(const float4*)&Bs[kk][tc * 8 + 4];
            float am[8] = {a0.x, a0.y, a0.z, a0.w, a1.x, a1.y, a1.z, a1.w};
            float bn[8] = {b0.x, b0.y, b0.z, b0.w, b1.x, b1.y, b1.z, b1.w};
#pragma unroll
            for (int i = 0; i < 8; i++)
#pragma unroll
                for (int j = 0; j < 8; j++) acc[i][j] = fmaf(am[i], bn[j], acc[i][j]);
        }
        __syncthreads();
    }
#pragma unroll
    for (int i = 0; i < 8; i++) {
        int m = m0 + tr * 8 + i;
#pragma unroll
        for (int j = 0; j < 8; j++) {
            int n = n0 + tc * 8 + j;
            float v = acc[i][j] + bias[n];
            if (RELU) v = fmaxf(v, 0.f);
            C[(size_t)m * N + n] = v;
        }
    }
}

// ---------------- attention ----------------
__device__ __forceinline__ float warp_max(float v) {
#pragma unroll
    for (int o = 16; o > 0; o >>= 1) v = fmaxf(v, __shfl_xor_sync(0xffffffffu, v, o));
    return v;
}
__device__ __forceinline__ float warp_sum(float v) {
#pragma unroll
    for (int o = 16; o > 0; o >>= 1) v += __shfl_xor_sync(0xffffffffu, v, o);
    return v;
}

template <int NK>
__device__ void attn_body(int n, int lane, int w,
                          const float* __restrict__ Ksh,
                          const float* __restrict__ Wqb_sh,
                          float* __restrict__ Qw,
                          float* __restrict__ avgw,
                          const unsigned* __restrict__ hpack,
                          float bq0, float bq1)
{
    float aacc[NK];
#pragma unroll
    for (int k = 0; k < NK; k++) aacc[k] = 0.f;

    for (int tb = 0; tb < n; tb += 16) {
        int tvalid = 0;
#pragma unroll
        for (int ii = 0; ii < 4; ii++) {
            int t = tb + 4 * ii + w;
            if (t < n) {
                unsigned hp = hpack[t];
                float q0 = bq0, q1 = bq1;
#pragma unroll
                for (int j = 0; j < 8; j++) {
                    int hh = (hp >> (3 * j)) & 7;
                    const float* wb = &Wqb_sh[(j * 8 + hh) * 64];
                    q0 += wb[lane];
                    q1 += wb[lane + 32];
                }
                Qw[(w * 4 + ii) * 64 + lane] = q0;
                Qw[(w * 4 + ii) * 64 + 32 + lane] = q1;
                tvalid = ii + 1;
            }
        }
        __syncwarp();

        float sc[4][NK];
#pragma unroll
        for (int ii = 0; ii < 4; ii++)
#pragma unroll
            for (int k = 0; k < NK; k++) sc[ii][k] = 0.f;

        for (int c = 0; c < 64; c++) {
            float kv[NK];
#pragma unroll
            for (int k = 0; k < NK; k++) kv[k] = Ksh[(lane + 32 * k) * KSTRIDE + c];
#pragma unroll
            for (int ii = 0; ii < 4; ii++) {
                float q = Qw[(w * 4 + ii) * 64 + c];
#pragma unroll
                for (int k = 0; k < NK; k++) sc[ii][k] = fmaf(q, kv[k], sc[ii][k]);
            }
        }

#pragma unroll
        for (int ii = 0; ii < 4; ii++) {
            if (ii >= tvalid) break;
            float m = -1e30f;
#pragma unroll
            for (int k = 0; k < NK; k++) {
                float v = (lane + 32 * k < n) ? sc[ii][k] * 0.125f : -1e30f;
                sc[ii][k] = v;
                m = fmaxf(m, v);
            }
            m = warp_max(m);
            float lsum = 0.f;
#pragma unroll
            for (int k = 0; k < NK; k++) {
                float e = __expf(sc[ii][k] - m);
                sc[ii][k] = e;
                lsum += e;
            }
            float inv = 1.0f / warp_sum(lsum);
#pragma unroll
            for (int k = 0; k < NK; k++) aacc[k] += sc[ii][k] * inv;
        }
        __syncwarp();
    }
#pragma unroll
    for (int k = 0; k < NK; k++) {
        int s = lane + 32 * k;
        if (s < n) atomicAdd(&avgw[s], aacc[k]);
    }
}

#define ATT_SMEM (17984 * 4)

__global__ void __launch_bounds__(128) attn_kernel(const float* __restrict__ bq)
{
    int g = blockIdx.x, h = blockIdx.y;
    int ntrue = g_counts[g];
    int off = g_offsets[g];
    extern __shared__ float sm[];
    float* Ksh    = sm;
    float* Wqb_sh = Ksh + MAX_N * KSTRIDE;
    float* Qw     = Wqb_sh + 4096;
    float* avgw   = Qw + 1024;
    unsigned* hpack = (unsigned*)(avgw + MAX_N);

    int tid = threadIdx.x, lane = tid & 31, w = tid >> 5;

    if (ntrue <= 0) {
        if (tid < 64) g_pooled[g * DIM + h * 64 + tid] = 0.f;
        return;
    }
    int n = ntrue < MAX_N ? ntrue : MAX_N;

    for (int idx = tid; idx < n * 64; idx += 128) {
        int s = idx >> 6, c = idx & 63;
        Ksh[s * KSTRIDE + c] = g_KV[(size_t)(off + s) * 1024 + h * 64 + c];
    }
    for (int idx = tid; idx < 4096; idx += 128) Wqb_sh[idx] = g_Wqb[h * 4096 + idx];
    for (int idx = tid; idx < MAX_N; idx += 128) avgw[idx] = 0.f;
    for (int t = tid; t < n; t += 128) {
        unsigned p = 0;
#pragma unroll
        for (int j = 0; j < 8; j++) {
            unsigned hh = (unsigned)(8 * t + j) / (unsigned)ntrue;
            p |= hh << (3 * j);
        }
        hpack[t] = p;
    }
    __syncthreads();

    float bq0 = bq[h * 64 + lane], bq1 = bq[h * 64 + 32 + lane];
    int nk = (n + 31) >> 5;
    switch (nk) {
        case 1: attn_body<1>(n, lane, w, Ksh, Wqb_sh, Qw, avgw, hpack, bq0, bq1); break;
        case 2: attn_body<2>(n, lane, w, Ksh, Wqb_sh, Qw, avgw, hpack, bq0, bq1); break;
        case 3: attn_body<3>(n, lane, w, Ksh, Wqb_sh, Qw, avgw, hpack, bq0, bq1); break;
        case 4: attn_body<4>(n, lane, w, Ksh, Wqb_sh, Qw, avgw, hpack, bq0, bq1); break;
        case 5: attn_body<5>(n, lane, w, Ksh, Wqb_sh, Qw, avgw, hpack, bq0, bq1); break;
        default: attn_body<6>(n, lane, w, Ksh, Wqb_sh, Qw, avgw, hpack, bq0, bq1); break;
    }
    __syncthreads();

    int c = tid & 63, half = tid >> 6;
    float acc = 0.f;
    const float* Vb = &g_KV[(size_t)off * 1024 + 512 + h * 64 + c];
    for (int s = half; s < n; s += 2) acc = fmaf(avgw[s], Vb[(size_t)s * 1024], acc);
    if (half) Qw[c] = acc;
    __syncthreads();
    if (!half) g_pooled[g * DIM + h * 64 + c] = (acc + Qw[c]) / (float)ntrue;
}

// ---------------- host launcher ----------------
extern "C" void kernel_launch(void* const* d_in, const int* in_sizes, int n_in,
                              void* d_out, int out_size)
{
    const float* x  = (const float*)d_in[0];
    const int*   bi = (const int*)  d_in[1];
    const float* gq = (const float*)d_in[2];
    const float* wq = (const float*)d_in[3];
    const float* bq = (const float*)d_in[4];
    const float* wk = (const float*)d_in[5];
    const float* bk = (const float*)d_in[6];
    const float* wv = (const float*)d_in[7];
    const float* bv = (const float*)d_in[8];
    const float* wo = (const float*)d_in[9];
    const float* bo = (const float*)d_in[10];
    const float* wp = (const float*)d_in[11];
    const float* bp = (const float*)d_in[12];
    float* out = (float*)d_out;

    void *pPooled, *pTmp;
    cudaGetSymbolAddress(&pPooled, g_pooled);
    cudaGetSymbolAddress(&pTmp, g_tmp);

    cudaFuncSetAttribute(attn_kernel, cudaFuncAttributeMaxDynamicSharedMemorySize, ATT_SMEM);
    cudaFuncSetAttribute(kv_gemm_kernel, cudaFuncAttributeMaxDynamicSharedMemorySize, GEMM_SMEM);

    convx_kernel<<<32768, 256>>>(x);
    convw_kernel<<<512, 256>>>(wk, wv);
    counts_kernel<<<1, NUM_G>>>(bi, bk, bv);
    wqb_kernel<<<dim3(HEADS, 8), 512>>>(gq, wq);

    // K/V projection: nodes x channels, bf16 mma.sync with compensation
    kv_gemm_kernel<<<dim3(1024 / BN, N_NODES / BM), 256, GEMM_SMEM>>>();

    attn_kernel<<<dim3(NUM_G, HEADS), 128, ATT_SMEM>>>(bq);

    sgemm_bias_kernel<false><<<dim3(4, 4), 256>>>(
        (const float*)pPooled, wo, bo, (float*)pTmp, NUM_G, DIM, DIM);
    sgemm_bias_kernel<true><<<dim3(4, 4), 256>>>(
        (const float*)pTmp, wp, bp, out, NUM_G, DIM, DIM);
}

// round 4
// speedup vs baseline: 1.9185x; 1.1576x over previous
#include <cuda_runtime.h>
#include <cuda_bf16.h>
#include <math.h>
#include <stdint.h>

#define N_NODES   65536
#define NUM_G     512
#define MAX_N     192
#define DIM       512
#define HEADS     8
#define DH        64
#define KSTRIDE   65

// ---- K/V projection GEMM config (mma.sync bf16, 3-term error compensation) ----
#define BM 128
#define BN 128
#define NCHUNK 24        // 3 passes x 512/64
#define STAGES 3
#define STG_BYTES 32768  // A 16KB + B 16KB
#define GEMM_SMEM (STAGES * STG_BYTES)

// ---------------- device scratch ----------------
__device__ float         g_KV[(size_t)N_NODES * 1024];   // [node][0:512]=K,[512:1024]=V
__device__ __nv_bfloat16 g_Xx[(size_t)N_NODES * 1024];   // [node][0:512]=hi,[512:1024]=lo
__device__ __nv_bfloat16 g_Wx[(size_t)1024 * 1024];      // [ch(wk;wv)][0:512]=hi,[512:1024]=lo
__device__ float         g_bKV[1024];
__device__ float         g_Wqb[HEADS * 8 * 8 * 64];
__device__ float         g_pooled[NUM_G * DIM];
__device__ float         g_tmp[NUM_G * DIM];
__device__ int           g_counts[NUM_G];
__device__ int           g_offsets[NUM_G];

// ---------------- helpers ----------------
__device__ __forceinline__ uint32_t smem_u32(const void* p) {
    uint32_t a;
    asm("{ .reg .u64 t; cvta.to.shared.u64 t, %1; cvt.u32.u64 %0, t; }" : "=r"(a) : "l"(p));
    return a;
}
#define SWZ(b) ((b) ^ (((b) >> 3) & 0x70))

__device__ __forceinline__ void cp_async16(uint32_t dst, const void* src) {
    asm volatile("cp.async.cg.shared.global [%0], [%1], 16;" :: "r"(dst), "l"(src));
}
__device__ __forceinline__ void cp_commit() {
    asm volatile("cp.async.commit_group;" ::: "memory");
}
template <int N> __device__ __forceinline__ void cp_wait() {
    asm volatile("cp.async.wait_group %0;" :: "n"(N) : "memory");
}
__device__ __forceinline__ void ldm_x4(uint32_t& r0, uint32_t& r1, uint32_t& r2, uint32_t& r3,
                                       uint32_t addr) {
    asm volatile("ldmatrix.sync.aligned.m8n8.x4.shared.b16 {%0,%1,%2,%3}, [%4];"
                 : "=r"(r0), "=r"(r1), "=r"(r2), "=r"(r3) : "r"(addr));
}
__device__ __forceinline__ void mma_bf16(float& d0, float& d1, float& d2, float& d3,
                                         uint32_t a0, uint32_t a1, uint32_t a2, uint32_t a3,
                                         uint32_t b0, uint32_t b1) {
    asm volatile("mma.sync.aligned.m16n8k16.row.col.f32.bf16.bf16.f32 "
                 "{%0,%1,%2,%3}, {%4,%5,%6,%7}, {%8,%9}, {%0,%1,%2,%3};"
                 : "+f"(d0), "+f"(d1), "+f"(d2), "+f"(d3)
                 : "r"(a0), "r"(a1), "r"(a2), "r"(a3), "r"(b0), "r"(b1));
}

// ---------------- counts/offsets + bias concat ----------------
__global__ void counts_kernel(const int* __restrict__ bidx,
                              const float* __restrict__ bk, const float* __restrict__ bv) {
    __shared__ int lb[NUM_G + 1];
    int g = threadIdx.x;
    int lo = 0, hi = N_NODES;
    while (lo < hi) { int mid = (lo + hi) >> 1; if (bidx[mid] < g) lo = mid + 1; else hi = mid; }
    lb[g] = lo;
    if (g == 0) lb[NUM_G] = N_NODES;
    __syncthreads();
    g_offsets[g] = lb[g];
    g_counts[g]  = lb[g + 1] - lb[g];
    g_bKV[g] = bk[g];
    g_bKV[512 + g] = bv[g];
}

// ---------------- fp32 -> bf16 hi/lo splits ----------------
__device__ __forceinline__ void split4(float4 v, uint2* hi, uint2* lo) {
    __nv_bfloat16 h0 = __float2bfloat16_rn(v.x), h1 = __float2bfloat16_rn(v.y);
    __nv_bfloat16 h2 = __float2bfloat16_rn(v.z), h3 = __float2bfloat16_rn(v.w);
    __nv_bfloat16 l0 = __float2bfloat16_rn(v.x - __bfloat162float(h0));
    __nv_bfloat16 l1 = __float2bfloat16_rn(v.y - __bfloat162float(h1));
    __nv_bfloat16 l2 = __float2bfloat16_rn(v.z - __bfloat162float(h2));
    __nv_bfloat16 l3 = __float2bfloat16_rn(v.w - __bfloat162float(h3));
    hi->x = (uint32_t)__bfloat16_as_ushort(h0) | ((uint32_t)__bfloat16_as_ushort(h1) << 16);
    hi->y = (uint32_t)__bfloat16_as_ushort(h2) | ((uint32_t)__bfloat16_as_ushort(h3) << 16);
    lo->x = (uint32_t)__bfloat16_as_ushort(l0) | ((uint32_t)__bfloat16_as_ushort(l1) << 16);
    lo->y = (uint32_t)__bfloat16_as_ushort(l2) | ((uint32_t)__bfloat16_as_ushort(l3) << 16);
}

__global__ void __launch_bounds__(256) convx_kernel(const float* __restrict__ x) {
    size_t i = (size_t)blockIdx.x * 256 + threadIdx.x;   // 65536*128 float4 units
    float4 v = ((const float4*)x)[i];
    size_t r = i >> 7;
    int c4 = (int)(i & 127);
    uint2 hi, lo;
    split4(v, &hi, &lo);
    ((uint2*)(g_Xx + r * 1024))[c4]       = hi;
    ((uint2*)(g_Xx + r * 1024 + 512))[c4] = lo;
}

__global__ void __launch_bounds__(256) convw_kernel(const float* __restrict__ wk,
                                                    const float* __restrict__ wv) {
    int i = blockIdx.x * 256 + threadIdx.x;              // 1024*128 float4 units
    int r = i >> 7;
    int c4 = i & 127;
    float4 v = (r < 512) ? ((const float4*)wk)[(size_t)r * 128 + c4]
                         : ((const float4*)wv)[(size_t)(r - 512) * 128 + c4];
    uint2 hi, lo;
    split4(v, &hi, &lo);
    ((uint2*)(g_Wx + (size_t)r * 1024))[c4]       = hi;
    ((uint2*)(g_Wx + (size_t)r * 1024 + 512))[c4] = lo;
}

// ---------------- Wqb precompute ----------------
__global__ void __launch_bounds__(512) wqb_kernel(const float* __restrict__ gq,
                                                  const float* __restrict__ wq) {
    int h = blockIdx.x, j = blockIdx.y;
    __shared__ float gqs[512];
    __shared__ float wsh[64 * 65];
    int tid = threadIdx.x;
    gqs[tid] = gq[tid];
    for (int idx = tid; idx < 64 * 64; idx += 512) {
        int row = idx >> 6, cc = idx & 63;
        wsh[row * 65 + cc] = wq[(size_t)(h * 64 + row) * 512 + j * 64 + cc];
    }
    __syncthreads();
    int ol = tid & 63, hh = tid >> 6;
    float v = 0.f;
#pragma unroll 8
    for (int r = 0; r < 64; r++) v += gqs[hh * 64 + r] * wsh[ol * 65 + r];
    g_Wqb[h * 4096 + (j * 8 + hh) * 64 + ol] = v;
}

// ---------------- bf16 mma.sync K/V GEMM ----------------
// chunk c: c 0-7: Whi*Xhi  c 8-15: Wlo*Xhi  c 16-23: Whi*Xlo
__device__ __forceinline__ void gemm_load_chunk(uint32_t sA, uint32_t sB,
                                                int m0, int n0, int c, int tid) {
    int kq = (c & 7) * 64;
    int kx = kq + ((c >= 16) ? 512 : 0);
    int kw = kq + ((c >= 8 && c < 16) ? 512 : 0);
#pragma unroll
    for (int u = 0; u < 4; u++) {
        int idx = tid + u * 256;         // 1024 x 16B = 16KB
        int row = idx >> 3;
        int cb = (idx & 7) * 16;
        cp_async16(sA + SWZ(row * 128 + cb),
                   (const char*)(g_Xx + (size_t)(m0 + row) * 1024 + kx) + cb);
    }
#pragma unroll
    for (int u = 0; u < 4; u++) {
        int idx = tid + u * 256;
        int row = idx >> 3;
        int cb = (idx & 7) * 16;
        cp_async16(sB + SWZ(row * 128 + cb),
                   (const char*)(g_Wx + (size_t)(n0 + row) * 1024 + kw) + cb);
    }
    cp_commit();
}

__global__ void __launch_bounds__(256, 2) kv_gemm_kernel() {
    extern __shared__ char smem[];
    uint32_t sbase = smem_u32(smem);
    int tid = threadIdx.x;
    int lane = tid & 31, w = tid >> 5;
    int wm = w >> 2, wn = w & 3;                 // 2 x 4 warp grid
    int m0 = blockIdx.y * BM;                    // nodes
    int n0 = blockIdx.x * BN;                    // channels

    float acc[4][4][4];
#pragma unroll
    for (int i = 0; i < 4; i++)
#pragma unroll
        for (int j = 0; j < 4; j++)
#pragma unroll
            for (int k = 0; k < 4; k++) acc[i][j][k] = 0.f;

    gemm_load_chunk(sbase, sbase + 16384, m0, n0, 0, tid);
    gemm_load_chunk(sbase + STG_BYTES, sbase + STG_BYTES + 16384, m0, n0, 1, tid);

    int lrow = ((lane >> 3) & 1) * 8 + (lane & 7);   // ldmatrix row within 16
    int lcol = ((lane >> 4) & 1) * 16;               // 16B col within 32B kstep

    for (int c = 0; c < NCHUNK; c++) {
        if (c < NCHUNK - 1) cp_wait<1>(); else cp_wait<0>();
        __syncthreads();
        if (c + 2 < NCHUNK) {
            uint32_t st = sbase + ((c + 2) % STAGES) * STG_BYTES;
            gemm_load_chunk(st, st + 16384, m0, n0, c + 2, tid);
        }
        uint32_t sA = sbase + (c % STAGES) * STG_BYTES;
        uint32_t sB = sA + 16384;

#pragma unroll
        for (int ks = 0; ks < 4; ks++) {
            uint32_t a[4][4], b[2][4];
#pragma unroll
            for (int mt = 0; mt < 4; mt++) {
                uint32_t addr = sA + SWZ((wm * 64 + mt * 16 + lrow) * 128 + ks * 32 + lcol);
                ldm_x4(a[mt][0], a[mt][1], a[mt][2], a[mt][3], addr);
            }
#pragma unroll
            for (int nt = 0; nt < 2; nt++) {
                uint32_t addr = sB + SWZ((wn * 32 + nt * 16 + lrow) * 128 + ks * 32 + lcol);
                ldm_x4(b[nt][0], b[nt][1], b[nt][2], b[nt][3], addr);
            }
#pragma unroll
            for (int mt = 0; mt < 4; mt++)
#pragma unroll
                for (int nt = 0; nt < 4; nt++) {
                    uint32_t b0 = b[nt >> 1][(nt & 1) ? 1 : 0];
                    uint32_t b1 = b[nt >> 1][(nt & 1) ? 3 : 2];
                    mma_bf16(acc[mt][nt][0], acc[mt][nt][1], acc[mt][nt][2], acc[mt][nt][3],
                             a[mt][0], a[mt][1], a[mt][2], a[mt][3], b0, b1);
                }
        }
    }

    int mrow = lane >> 2;
    int ncol = (lane & 3) * 2;
#pragma unroll
    for (int mt = 0; mt < 4; mt++) {
#pragma unroll
        for (int nt = 0; nt < 4; nt++) {
            int m = m0 + wm * 64 + mt * 16 + mrow;
            int n = n0 + wn * 32 + nt * 8 + ncol;
            float2 bias = *(const float2*)&g_bKV[n];
            float2 v0 = make_float2(acc[mt][nt][0] + bias.x, acc[mt][nt][1] + bias.y);
            float2 v1 = make_float2(acc[mt][nt][2] + bias.x, acc[mt][nt][3] + bias.y);
            *(float2*)&g_KV[(size_t)m * 1024 + n] = v0;
            *(float2*)&g_KV[(size_t)(m + 8) * 1024 + n] = v1;
        }
    }
}

// ---------------- small SGEMM (output projections) ----------------
template <bool RELU>
__global__ void __launch_bounds__(256) sgemm_bias_kernel(
    const float* __restrict__ A, const float* __restrict__ B,
    const float* __restrict__ bias, float* __restrict__ C,
    int M, int N, int K)
{
    const int BKK = 16;
    __shared__ float As[BKK][128];
    __shared__ float Bs[BKK][128];
    int tid = threadIdx.x;
    int m0 = blockIdx.y * 128;
    int n0 = blockIdx.x * 128;
    int tr = tid >> 4, tc = tid & 15;
    int lr = tid >> 2;
    int lc = (tid & 3) * 4;
    float acc[8][8];
#pragma unroll
    for (int i = 0; i < 8; i++)
#pragma unroll
        for (int j = 0; j < 8; j++) acc[i][j] = 0.f;

    for (int k0 = 0; k0 < K; k0 += BKK) {
#pragma unroll
        for (int p = 0; p < 2; p++) {
            int r = lr + p * 64;
            float4 a = *(const float4*)(A + (size_t)(m0 + r) * K + k0 + lc);
            As[lc + 0][r] = a.x; As[lc + 1][r] = a.y; As[lc + 2][r] = a.z; As[lc + 3][r] = a.w;
            float4 b = *(const float4*)(B + (size_t)(n0 + r) * K + k0 + lc);
            Bs[lc + 0][r] = b.x; Bs[lc + 1][r] = b.y; Bs[lc + 2][r] = b.z; Bs[lc + 3][r] = b.w;
        }
        __syncthreads();
#pragma unroll
        for (int kk = 0; kk < BKK; kk++) {
            float4 a0 = *(const float4*)&As[kk][tr * 8];
            float4 a1 = *(const float4*)&As[kk][tr * 8 + 4];
            float4 b0 = *(const float4*)&Bs[kk][tc * 8];
            float4 b1 = *(const float4*)&Bs[kk][tc * 8 + 4];
            float am[8] = {a0.x, a0.y, a0.z, a0.w, a1.x, a1.y, a1.z, a1.w};
            float bn[8] = {b0.x, b0.y, b0.z, b0.w, b1.x, b1.y, b1.z, b1.w};
#pragma unroll
            for (int i = 0; i < 8; i++)
#pragma unroll
                for (int j = 0; j < 8; j++) acc[i][j] = fmaf(am[i], bn[j], acc[i][j]);
        }
        __syncthreads();
    }
#pragma unroll
    for (int i = 0; i < 8; i++) {
        int m = m0 + tr * 8 + i;
#pragma unroll
        for (int j = 0; j < 8; j++) {
            int n = n0 + tc * 8 + j;
            float v = acc[i][j] + bias[n];
            if (RELU) v = fmaxf(v, 0.f);
            C[(size_t)m * N + n] = v;
        }
    }
}

// ---------------- attention (256 threads, 8 warps) ----------------
__device__ __forceinline__ float warp_max(float v) {
#pragma unroll
    for (int o = 16; o > 0; o >>= 1) v = fmaxf(v, __shfl_xor_sync(0xffffffffu, v, o));
    return v;
}
__device__ __forceinline__ float warp_sum(float v) {
#pragma unroll
    for (int o = 16; o > 0; o >>= 1) v += __shfl_xor_sync(0xffffffffu, v, o);
    return v;
}

template <int NK>
__device__ void attn_body(int n, int lane, int w,
                          const float* __restrict__ Ksh,
                          const float* __restrict__ Wqb_sh,
                          float* __restrict__ Qw,
                          float* __restrict__ avgw,
                          const unsigned* __restrict__ hpack,
                          float bq0, float bq1)
{
    float aacc[NK];
#pragma unroll
    for (int k = 0; k < NK; k++) aacc[k] = 0.f;

    for (int tb = 0; tb < n; tb += 32) {
        int tvalid = 0;
#pragma unroll
        for (int ii = 0; ii < 4; ii++) {
            int t = tb + 8 * ii + w;
            if (t < n) {
                unsigned hp = hpack[t];
                float q0 = bq0, q1 = bq1;
#pragma unroll
                for (int j = 0; j < 8; j++) {
                    int hh = (hp >> (3 * j)) & 7;
                    const float* wb = &Wqb_sh[(j * 8 + hh) * 64];
                    q0 += wb[lane];
                    q1 += wb[lane + 32];
                }
                Qw[(w * 4 + ii) * 64 + lane] = q0;
                Qw[(w * 4 + ii) * 64 + 32 + lane] = q1;
                tvalid = ii + 1;
            }
        }
        __syncwarp();

        float sc[4][NK];
#pragma unroll
        for (int ii = 0; ii < 4; ii++)
#pragma unroll
            for (int k = 0; k < NK; k++) sc[ii][k] = 0.f;

        for (int c = 0; c < 64; c++) {
            float kv[NK];
#pragma unroll
            for (int k = 0; k < NK; k++) kv[k] = Ksh[(lane + 32 * k) * KSTRIDE + c];
#pragma unroll
            for (int ii = 0; ii < 4; ii++) {
                float q = Qw[(w * 4 + ii) * 64 + c];
#pragma unroll
                for (int k = 0; k < NK; k++) sc[ii][k] = fmaf(q, kv[k], sc[ii][k]);
            }
        }

#pragma unroll
        for (int ii = 0; ii < 4; ii++) {
            if (ii >= tvalid) break;
            float m = -1e30f;
#pragma unroll
            for (int k = 0; k < NK; k++) {
                float v = (lane + 32 * k < n) ? sc[ii][k] * 0.125f : -1e30f;
                sc[ii][k] = v;
                m = fmaxf(m, v);
            }
            m = warp_max(m);
            float lsum = 0.f;
#pragma unroll
            for (int k = 0; k < NK; k++) {
                float e = __expf(sc[ii][k] - m);
                sc[ii][k] = e;
                lsum += e;
            }
            float inv = 1.0f / warp_sum(lsum);
#pragma unroll
            for (int k = 0; k < NK; k++) aacc[k] += sc[ii][k] * inv;
        }
        __syncwarp();
    }
#pragma unroll
    for (int k = 0; k < NK; k++) {
        int s = lane + 32 * k;
        if (s < n) atomicAdd(&avgw[s], aacc[k]);
    }
}

// smem: Ksh 192*65 + Wqb 4096 + Qw 2048 + avgw 192 + hpack 192 = 19008 floats
#define ATT_SMEM (19008 * 4)

__global__ void __launch_bounds__(256) attn_kernel(const float* __restrict__ bq)
{
    int g = blockIdx.x, h = blockIdx.y;
    int ntrue = g_counts[g];
    int off = g_offsets[g];
    extern __shared__ float sm[];
    float* Ksh    = sm;
    float* Wqb_sh = Ksh + MAX_N * KSTRIDE;
    float* Qw     = Wqb_sh + 4096;            // 32*64
    float* avgw   = Qw + 2048;
    unsigned* hpack = (unsigned*)(avgw + MAX_N);

    int tid = threadIdx.x, lane = tid & 31, w = tid >> 5;

    if (ntrue <= 0) {
        if (tid < 64) g_pooled[g * DIM + h * 64 + tid] = 0.f;
        return;
    }
    int n = ntrue < MAX_N ? ntrue : MAX_N;

    for (int idx = tid; idx < n * 64; idx += 256) {
        int s = idx >> 6, c = idx & 63;
        Ksh[s * KSTRIDE + c] = g_KV[(size_t)(off + s) * 1024 + h * 64 + c];
    }
    for (int idx = tid; idx < 4096; idx += 256) Wqb_sh[idx] = g_Wqb[h * 4096 + idx];
    for (int idx = tid; idx < MAX_N; idx += 256) avgw[idx] = 0.f;
    for (int t = tid; t < n; t += 256) {
        unsigned p = 0;
#pragma unroll
        for (int j = 0; j < 8; j++) {
            unsigned hh = (unsigned)(8 * t + j) / (unsigned)ntrue;
            p |= hh << (3 * j);
        }
        hpack[t] = p;
    }
    __syncthreads();

    float bq0 = bq[h * 64 + lane], bq1 = bq[h * 64 + 32 + lane];
    int nk = (n + 31) >> 5;
    switch (nk) {
        case 1: attn_body<1>(n, lane, w, Ksh, Wqb_sh, Qw, avgw, hpack, bq0, bq1); break;
        case 2: attn_body<2>(n, lane, w, Ksh, Wqb_sh, Qw, avgw, hpack, bq0, bq1); break;
        case 3: attn_body<3>(n, lane, w, Ksh, Wqb_sh, Qw, avgw, hpack, bq0, bq1); break;
        case 4: attn_body<4>(n, lane, w, Ksh, Wqb_sh, Qw, avgw, hpack, bq0, bq1); break;
        case 5: attn_body<5>(n, lane, w, Ksh, Wqb_sh, Qw, avgw, hpack, bq0, bq1); break;
        default: attn_body<6>(n, lane, w, Ksh, Wqb_sh, Qw, avgw, hpack, bq0, bq1); break;
    }
    __syncthreads();

    // epilogue: 4-way split V-weighted sum, reduce via smem
    int c = tid & 63, part = tid >> 6;
    float acc = 0.f;
    const float* Vb = &g_KV[(size_t)off * 1024 + 512 + h * 64 + c];
    for (int s = part; s < n; s += 4) acc = fmaf(avgw[s], Vb[(size_t)s * 1024], acc);
    if (part) Qw[(part - 1) * 64 + c] = acc;
    __syncthreads();
    if (!part)
        g_pooled[g * DIM + h * 64 + c] =
            (acc + Qw[c] + Qw[64 + c] + Qw[128 + c]) / (float)ntrue;
}

// ---------------- host launcher ----------------
extern "C" void kernel_launch(void* const* d_in, const int* in_sizes, int n_in,
                              void* d_out, int out_size)
{
    const float* x  = (const float*)d_in[0];
    const int*   bi = (const int*)  d_in[1];
    const float* gq = (const float*)d_in[2];
    const float* wq = (const float*)d_in[3];
    const float* bq = (const float*)d_in[4];
    const float* wk = (const float*)d_in[5];
    const float* bk = (const float*)d_in[6];
    const float* wv = (const float*)d_in[7];
    const float* bv = (const float*)d_in[8];
    const float* wo = (const float*)d_in[9];
    const float* bo = (const float*)d_in[10];
    const float* wp = (const float*)d_in[11];
    const float* bp = (const float*)d_in[12];
    float* out = (float*)d_out;

    void *pPooled, *pTmp;
    cudaGetSymbolAddress(&pPooled, g_pooled);
    cudaGetSymbolAddress(&pTmp, g_tmp);

    cudaFuncSetAttribute(attn_kernel, cudaFuncAttributeMaxDynamicSharedMemorySize, ATT_SMEM);
    cudaFuncSetAttribute(kv_gemm_kernel, cudaFuncAttributeMaxDynamicSharedMemorySize, GEMM_SMEM);

    // order chosen so the profiled launch slot lands on kv_gemm_kernel
    convx_kernel<<<32768, 256>>>(x);
    convw_kernel<<<512, 256>>>(wk, wv);
    counts_kernel<<<1, NUM_G>>>(bi, bk, bv);

    kv_gemm_kernel<<<dim3(1024 / BN, N_NODES / BM), 256, GEMM_SMEM>>>();

    wqb_kernel<<<dim3(HEADS, 8), 512>>>(gq, wq);

    attn_kernel<<<dim3(NUM_G, HEADS), 256, ATT_SMEM>>>(bq);

    sgemm_bias_kernel<false><<<dim3(4, 4), 256>>>(
        (const float*)pPooled, wo, bo, (float*)pTmp, NUM_G, DIM, DIM);
    sgemm_bias_kernel<true><<<dim3(4, 4), 256>>>(
        (const float*)pTmp, wp, bp, out, NUM_G, DIM, DIM);
}

// round 5
// speedup vs baseline: 2.7698x; 1.4437x over previous
#include <cuda_runtime.h>
#include <cuda_bf16.h>
#include <math.h>
#include <stdint.h>

#define N_NODES   65536
#define NUM_G     512
#define MAX_N     192
#define DIM       512
#define HEADS     8
#define DH        64
#define KSTRIDE   65

// ---- K/V projection GEMM config ----
#define BM 128
#define BN 128
#define NCHUNK 24
#define STAGES 3
#define STG_BYTES 32768
#define GEMM_SMEM (STAGES * STG_BYTES)

// ---------------- device scratch ----------------
__device__ float         g_KV[(size_t)N_NODES * 1024];
__device__ __nv_bfloat16 g_Xx[(size_t)N_NODES * 1024];
__device__ __nv_bfloat16 g_Wx[(size_t)1024 * 1024];
__device__ float         g_bKV[1024];
__device__ float         g_Wqb[HEADS * 8 * 8 * 64];
__device__ float         g_pooled[NUM_G * DIM];
__device__ float         g_tmp[NUM_G * DIM];
__device__ int           g_counts[NUM_G];
__device__ int           g_offsets[NUM_G];

// ---------------- helpers ----------------
__device__ __forceinline__ uint32_t smem_u32(const void* p) {
    uint32_t a;
    asm("{ .reg .u64 t; cvta.to.shared.u64 t, %1; cvt.u32.u64 %0, t; }" : "=r"(a) : "l"(p));
    return a;
}
#define SWZ(b) ((b) ^ (((b) >> 3) & 0x70))

__device__ __forceinline__ void cp_async16(uint32_t dst, const void* src) {
    asm volatile("cp.async.cg.shared.global [%0], [%1], 16;" :: "r"(dst), "l"(src));
}
__device__ __forceinline__ void cp_commit() {
    asm volatile("cp.async.commit_group;" ::: "memory");
}
template <int N> __device__ __forceinline__ void cp_wait() {
    asm volatile("cp.async.wait_group %0;" :: "n"(N) : "memory");
}
__device__ __forceinline__ void ldm_x4(uint32_t& r0, uint32_t& r1, uint32_t& r2, uint32_t& r3,
                                       uint32_t addr) {
    asm volatile("ldmatrix.sync.aligned.m8n8.x4.shared.b16 {%0,%1,%2,%3}, [%4];"
                 : "=r"(r0), "=r"(r1), "=r"(r2), "=r"(r3) : "r"(addr));
}
__device__ __forceinline__ void mma_bf16(float& d0, float& d1, float& d2, float& d3,
                                         uint32_t a0, uint32_t a1, uint32_t a2, uint32_t a3,
                                         uint32_t b0, uint32_t b1) {
    asm volatile("mma.sync.aligned.m16n8k16.row.col.f32.bf16.bf16.f32 "
                 "{%0,%1,%2,%3}, {%4,%5,%6,%7}, {%8,%9}, {%0,%1,%2,%3};"
                 : "+f"(d0), "+f"(d1), "+f"(d2), "+f"(d3)
                 : "r"(a0), "r"(a1), "r"(a2), "r"(a3), "r"(b0), "r"(b1));
}

// ---------------- counts/offsets + bias concat ----------------
__global__ void counts_kernel(const int* __restrict__ bidx,
                              const float* __restrict__ bk, const float* __restrict__ bv) {
    __shared__ int lb[NUM_G + 1];
    int g = threadIdx.x;
    int lo = 0, hi = N_NODES;
    while (lo < hi) { int mid = (lo + hi) >> 1; if (bidx[mid] < g) lo = mid + 1; else hi = mid; }
    lb[g] = lo;
    if (g == 0) lb[NUM_G] = N_NODES;
    __syncthreads();
    g_offsets[g] = lb[g];
    g_counts[g]  = lb[g + 1] - lb[g];
    g_bKV[g] = bk[g];
    g_bKV[512 + g] = bv[g];
}

// ---------------- fp32 -> bf16 hi/lo splits ----------------
__device__ __forceinline__ void split4(float4 v, uint2* hi, uint2* lo) {
    __nv_bfloat16 h0 = __float2bfloat16_rn(v.x), h1 = __float2bfloat16_rn(v.y);
    __nv_bfloat16 h2 = __float2bfloat16_rn(v.z), h3 = __float2bfloat16_rn(v.w);
    __nv_bfloat16 l0 = __float2bfloat16_rn(v.x - __bfloat162float(h0));
    __nv_bfloat16 l1 = __float2bfloat16_rn(v.y - __bfloat162float(h1));
    __nv_bfloat16 l2 = __float2bfloat16_rn(v.z - __bfloat162float(h2));
    __nv_bfloat16 l3 = __float2bfloat16_rn(v.w - __bfloat162float(h3));
    hi->x = (uint32_t)__bfloat16_as_ushort(h0) | ((uint32_t)__bfloat16_as_ushort(h1) << 16);
    hi->y = (uint32_t)__bfloat16_as_ushort(h2) | ((uint32_t)__bfloat16_as_ushort(h3) << 16);
    lo->x = (uint32_t)__bfloat16_as_ushort(l0) | ((uint32_t)__bfloat16_as_ushort(l1) << 16);
    lo->y = (uint32_t)__bfloat16_as_ushort(l2) | ((uint32_t)__bfloat16_as_ushort(l3) << 16);
}

__global__ void __launch_bounds__(256) convx_kernel(const float* __restrict__ x) {
    size_t i = (size_t)blockIdx.x * 256 + threadIdx.x;
    float4 v = ((const float4*)x)[i];
    size_t r = i >> 7;
    int c4 = (int)(i & 127);
    uint2 hi, lo;
    split4(v, &hi, &lo);
    ((uint2*)(g_Xx + r * 1024))[c4]       = hi;
    ((uint2*)(g_Xx + r * 1024 + 512))[c4] = lo;
}

__global__ void __launch_bounds__(256) convw_kernel(const float* __restrict__ wk,
                                                    const float* __restrict__ wv) {
    int i = blockIdx.x * 256 + threadIdx.x;
    int r = i >> 7;
    int c4 = i & 127;
    float4 v = (r < 512) ? ((const float4*)wk)[(size_t)r * 128 + c4]
                         : ((const float4*)wv)[(size_t)(r - 512) * 128 + c4];
    uint2 hi, lo;
    split4(v, &hi, &lo);
    ((uint2*)(g_Wx + (size_t)r * 1024))[c4]       = hi;
    ((uint2*)(g_Wx + (size_t)r * 1024 + 512))[c4] = lo;
}

// ---------------- Wqb precompute ----------------
__global__ void __launch_bounds__(512) wqb_kernel(const float* __restrict__ gq,
                                                  const float* __restrict__ wq) {
    int h = blockIdx.x, j = blockIdx.y;
    __shared__ float gqs[512];
    __shared__ float wsh[64 * 65];
    int tid = threadIdx.x;
    gqs[tid] = gq[tid];
    for (int idx = tid; idx < 64 * 64; idx += 512) {
        int row = idx >> 6, cc = idx & 63;
        wsh[row * 65 + cc] = wq[(size_t)(h * 64 + row) * 512 + j * 64 + cc];
    }
    __syncthreads();
    int ol = tid & 63, hh = tid >> 6;
    float v = 0.f;
#pragma unroll 8
    for (int r = 0; r < 64; r++) v += gqs[hh * 64 + r] * wsh[ol * 65 + r];
    g_Wqb[h * 4096 + (j * 8 + hh) * 64 + ol] = v;
}

// ---------------- bf16 mma.sync K/V GEMM ----------------
__device__ __forceinline__ void gemm_load_chunk(uint32_t sA, uint32_t sB,
                                                int m0, int n0, int c, int tid) {
    int kq = (c & 7) * 64;
    int kx = kq + ((c >= 16) ? 512 : 0);
    int kw = kq + ((c >= 8 && c < 16) ? 512 : 0);
#pragma unroll
    for (int u = 0; u < 4; u++) {
        int idx = tid + u * 256;
        int row = idx >> 3;
        int cb = (idx & 7) * 16;
        cp_async16(sA + SWZ(row * 128 + cb),
                   (const char*)(g_Xx + (size_t)(m0 + row) * 1024 + kx) + cb);
    }
#pragma unroll
    for (int u = 0; u < 4; u++) {
        int idx = tid + u * 256;
        int row = idx >> 3;
        int cb = (idx & 7) * 16;
        cp_async16(sB + SWZ(row * 128 + cb),
                   (const char*)(g_Wx + (size_t)(n0 + row) * 1024 + kw) + cb);
    }
    cp_commit();
}

__global__ void __launch_bounds__(256, 2) kv_gemm_kernel() {
    extern __shared__ char smem[];
    uint32_t sbase = smem_u32(smem);
    int tid = threadIdx.x;
    int lane = tid & 31, w = tid >> 5;
    int wm = w >> 2, wn = w & 3;
    int m0 = blockIdx.y * BM;
    int n0 = blockIdx.x * BN;

    float acc[4][4][4];
#pragma unroll
    for (int i = 0; i < 4; i++)
#pragma unroll
        for (int j = 0; j < 4; j++)
#pragma unroll
            for (int k = 0; k < 4; k++) acc[i][j][k] = 0.f;

    gemm_load_chunk(sbase, sbase + 16384, m0, n0, 0, tid);
    gemm_load_chunk(sbase + STG_BYTES, sbase + STG_BYTES + 16384, m0, n0, 1, tid);

    int lrow = ((lane >> 3) & 1) * 8 + (lane & 7);
    int lcol = ((lane >> 4) & 1) * 16;

    for (int c = 0; c < NCHUNK; c++) {
        if (c < NCHUNK - 1) cp_wait<1>(); else cp_wait<0>();
        __syncthreads();
        if (c + 2 < NCHUNK) {
            uint32_t st = sbase + ((c + 2) % STAGES) * STG_BYTES;
            gemm_load_chunk(st, st + 16384, m0, n0, c + 2, tid);
        }
        uint32_t sA = sbase + (c % STAGES) * STG_BYTES;
        uint32_t sB = sA + 16384;

#pragma unroll
        for (int ks = 0; ks < 4; ks++) {
            uint32_t a[4][4], b[2][4];
#pragma unroll
            for (int mt = 0; mt < 4; mt++) {
                uint32_t addr = sA + SWZ((wm * 64 + mt * 16 + lrow) * 128 + ks * 32 + lcol);
                ldm_x4(a[mt][0], a[mt][1], a[mt][2], a[mt][3], addr);
            }
#pragma unroll
            for (int nt = 0; nt < 2; nt++) {
                uint32_t addr = sB + SWZ((wn * 32 + nt * 16 + lrow) * 128 + ks * 32 + lcol);
                ldm_x4(b[nt][0], b[nt][1], b[nt][2], b[nt][3], addr);
            }
#pragma unroll
            for (int mt = 0; mt < 4; mt++)
#pragma unroll
                for (int nt = 0; nt < 4; nt++) {
                    uint32_t b0 = b[nt >> 1][(nt & 1) ? 1 : 0];
                    uint32_t b1 = b[nt >> 1][(nt & 1) ? 3 : 2];
                    mma_bf16(acc[mt][nt][0], acc[mt][nt][1], acc[mt][nt][2], acc[mt][nt][3],
                             a[mt][0], a[mt][1], a[mt][2], a[mt][3], b0, b1);
                }
        }
    }

    int mrow = lane >> 2;
    int ncol = (lane & 3) * 2;
#pragma unroll
    for (int mt = 0; mt < 4; mt++) {
#pragma unroll
        for (int nt = 0; nt < 4; nt++) {
            int m = m0 + wm * 64 + mt * 16 + mrow;
            int n = n0 + wn * 32 + nt * 8 + ncol;
            float2 bias = *(const float2*)&g_bKV[n];
            float2 v0 = make_float2(acc[mt][nt][0] + bias.x, acc[mt][nt][1] + bias.y);
            float2 v1 = make_float2(acc[mt][nt][2] + bias.x, acc[mt][nt][3] + bias.y);
            *(float2*)&g_KV[(size_t)m * 1024 + n] = v0;
            *(float2*)&g_KV[(size_t)(m + 8) * 1024 + n] = v1;
        }
    }
}

// ---------------- small SGEMM 64x64 tiles (better grid occupancy) ----------------
template <bool RELU>
__global__ void __launch_bounds__(128) sgemm64_kernel(
    const float* __restrict__ A, const float* __restrict__ B,
    const float* __restrict__ bias, float* __restrict__ C,
    int M, int N, int K)
{
    __shared__ float As[16][64];
    __shared__ float Bs[16][64];
    int tid = threadIdx.x;
    int m0 = blockIdx.y * 64;
    int n0 = blockIdx.x * 64;
    int tr = tid >> 3, tc = tid & 7;       // 16 x 8 thread grid, 4x8 per thread
    int lr = tid >> 2;                     // 32 rows per pass
    int lc = (tid & 3) * 4;
    float acc[4][8];
#pragma unroll
    for (int i = 0; i < 4; i++)
#pragma unroll
        for (int j = 0; j < 8; j++) acc[i][j] = 0.f;

    for (int k0 = 0; k0 < K; k0 += 16) {
#pragma unroll
        for (int p = 0; p < 2; p++) {
            int r = lr + 32 * p;
            float4 a = *(const float4*)(A + (size_t)(m0 + r) * K + k0 + lc);
            As[lc + 0][r] = a.x; As[lc + 1][r] = a.y; As[lc + 2][r] = a.z; As[lc + 3][r] = a.w;
            float4 b = *(const float4*)(B + (size_t)(n0 + r) * K + k0 + lc);
            Bs[lc + 0][r] = b.x; Bs[lc + 1][r] = b.y; Bs[lc + 2][r] = b.z; Bs[lc + 3][r] = b.w;
        }
        __syncthreads();
#pragma unroll
        for (int kk = 0; kk < 16; kk++) {
            float am[4], bn[8];
#pragma unroll
            for (int i = 0; i < 4; i++) am[i] = As[kk][tr * 4 + i];
#pragma unroll
            for (int j = 0; j < 8; j++) bn[j] = Bs[kk][tc * 8 + j];
#pragma unroll
            for (int i = 0; i < 4; i++)
#pragma unroll
                for (int j = 0; j < 8; j++) acc[i][j] = fmaf(am[i], bn[j], acc[i][j]);
        }
        __syncthreads();
    }
#pragma unroll
    for (int i = 0; i < 4; i++) {
        int m = m0 + tr * 4 + i;
#pragma unroll
        for (int j = 0; j < 8; j++) {
            int n = n0 + tc * 8 + j;
            float v = acc[i][j] + bias[n];
            if (RELU) v = fmaxf(v, 0.f);
            C[(size_t)m * N + n] = v;
        }
    }
}

// ---------------- attention with Q-class compression ----------------
__device__ __forceinline__ float warp_max(float v) {
#pragma unroll
    for (int o = 16; o > 0; o >>= 1) v = fmaxf(v, __shfl_xor_sync(0xffffffffu, v, o));
    return v;
}
__device__ __forceinline__ float warp_sum(float v) {
#pragma unroll
    for (int o = 16; o > 0; o >>= 1) v += __shfl_xor_sync(0xffffffffu, v, o);
    return v;
}

template <int NK>
__device__ void attn_classes(int n, int U, int lane, int w, int h,
                             const float* __restrict__ Ksh,
                             const float* __restrict__ Qcls,
                             const float* __restrict__ ucnt,
                             float* __restrict__ avgw)
{
    float aacc[NK];
#pragma unroll
    for (int k = 0; k < NK; k++) aacc[k] = 0.f;

    for (int u = w; u < U; u += 8) {
        float sc[NK];
#pragma unroll
        for (int k = 0; k < NK; k++) sc[k] = 0.f;
        const float* Qu = &Qcls[u * 64];
        for (int c = 0; c < 64; c++) {
            float q = Qu[c];
#pragma unroll
            for (int k = 0; k < NK; k++)
                sc[k] = fmaf(q, Ksh[(lane + 32 * k) * KSTRIDE + c], sc[k]);
        }
        float m = -1e30f;
#pragma unroll
        for (int k = 0; k < NK; k++) {
            float v = (lane + 32 * k < n) ? sc[k] * 0.125f : -1e30f;
            sc[k] = v;
            m = fmaxf(m, v);
        }
        m = warp_max(m);
        float lsum = 0.f;
#pragma unroll
        for (int k = 0; k < NK; k++) {
            float e = __expf(sc[k] - m);
            sc[k] = e;
            lsum += e;
        }
        float scale = ucnt[u] / warp_sum(lsum);
#pragma unroll
        for (int k = 0; k < NK; k++) aacc[k] += sc[k] * scale;
    }
#pragma unroll
    for (int k = 0; k < NK; k++) {
        int s = lane + 32 * k;
        if (s < n) atomicAdd(&avgw[s], aacc[k]);
    }
}

// smem floats: Ksh 12480 + Qcls 2048 + avgw 192 + hpack 192 + uhp 32 + ucnt 32 + scan 12
#define ATT_SMEM ((12480 + 2048 + 192 + 192 + 32 + 32 + 12) * 4)

__global__ void __launch_bounds__(256) attn_kernel(const float* __restrict__ bq)
{
    int g = blockIdx.x, h = blockIdx.y;
    int ntrue = g_counts[g];
    int off = g_offsets[g];
    extern __shared__ float sm[];
    float*    Ksh   = sm;                         // 192*65
    float*    Qcls  = Ksh + MAX_N * KSTRIDE;      // 32*64
    float*    avgw  = Qcls + 2048;                // 192
    unsigned* hpack = (unsigned*)(avgw + MAX_N);  // 192
    unsigned* uhp   = hpack + MAX_N;              // 32
    float*    ucnt  = (float*)(uhp + 32);         // 32
    int*      wcnt  = (int*)(ucnt + 32);          // 8 + 1(U) + pad

    int tid = threadIdx.x, lane = tid & 31, w = tid >> 5;

    if (ntrue <= 0) {
        if (tid < 64) g_pooled[g * DIM + h * 64 + tid] = 0.f;
        return;
    }
    int n = ntrue < MAX_N ? ntrue : MAX_N;

    for (int idx = tid; idx < n * 64; idx += 256) {
        int s = idx >> 6, c = idx & 63;
        Ksh[s * KSTRIDE + c] = g_KV[(size_t)(off + s) * 1024 + h * 64 + c];
    }
    for (int idx = tid; idx < MAX_N; idx += 256) avgw[idx] = 0.f;
    if (tid < 32) ucnt[tid] = 0.f;
    for (int t = tid; t < n; t += 256) {
        unsigned p = 0;
#pragma unroll
        for (int j = 0; j < 8; j++) {
            unsigned hh = (unsigned)(8 * t + j) / (unsigned)ntrue;
            p |= hh << (3 * j);
        }
        hpack[t] = p;
    }
    __syncthreads();

    // run-length classify hpack (boundaries -> class ids) via ballot scan
    int t = tid;
    int isb = (t < n) && (t == 0 || hpack[t] != hpack[t - 1]);
    unsigned bits = __ballot_sync(0xffffffffu, isb);
    if (lane == 31) wcnt[w] = __popc(bits);
    __syncthreads();
    if (tid == 0) {
        int s = 0;
#pragma unroll
        for (int i = 0; i < 8; i++) { int c = wcnt[i]; wcnt[i] = s; s += c; }
        wcnt[8] = s;                                  // U
    }
    __syncthreads();
    int U = wcnt[8];
    if (t < n) {
        int cid = wcnt[w] + __popc(bits & ((2u << lane) - 1u)) - 1;  // inclusive - 1
        if (isb) uhp[cid] = hpack[t];
        atomicAdd(&ucnt[cid], 1.0f);
    }
    __syncthreads();

    // build class Q vectors (each warp builds classes w, w+8, ...)
    float bq0 = bq[h * 64 + lane], bq1 = bq[h * 64 + 32 + lane];
    for (int u = w; u < U; u += 8) {
        unsigned hp = uhp[u];
        float q0 = bq0, q1 = bq1;
#pragma unroll
        for (int j = 0; j < 8; j++) {
            int hh = (hp >> (3 * j)) & 7;
            const float* wb = &g_Wqb[h * 4096 + (j * 8 + hh) * 64];
            q0 += wb[lane];
            q1 += wb[lane + 32];
        }
        Qcls[u * 64 + lane] = q0;
        Qcls[u * 64 + 32 + lane] = q1;
    }
    __syncthreads();

    int nk = (n + 31) >> 5;
    switch (nk) {
        case 1: attn_classes<1>(n, U, lane, w, h, Ksh, Qcls, ucnt, avgw); break;
        case 2: attn_classes<2>(n, U, lane, w, h, Ksh, Qcls, ucnt, avgw); break;
        case 3: attn_classes<3>(n, U, lane, w, h, Ksh, Qcls, ucnt, avgw); break;
        case 4: attn_classes<4>(n, U, lane, w, h, Ksh, Qcls, ucnt, avgw); break;
        case 5: attn_classes<5>(n, U, lane, w, h, Ksh, Qcls, ucnt, avgw); break;
        default: attn_classes<6>(n, U, lane, w, h, Ksh, Qcls, ucnt, avgw); break;
    }
    __syncthreads();

    // epilogue: pooled = (1/ntrue) * sum_s avgw[s] * V[off+s, :]
    int c = tid & 63, part = tid >> 6;
    float acc = 0.f;
    const float* Vb = &g_KV[(size_t)off * 1024 + 512 + h * 64 + c];
    for (int s = part; s < n; s += 4) acc = fmaf(avgw[s], Vb[(size_t)s * 1024], acc);
    if (part) Qcls[(part - 1) * 64 + c] = acc;
    __syncthreads();
    if (!part)
        g_pooled[g * DIM + h * 64 + c] =
            (acc + Qcls[c] + Qcls[64 + c] + Qcls[128 + c]) / (float)ntrue;
}

// ---------------- host launcher ----------------
extern "C" void kernel_launch(void* const* d_in, const int* in_sizes, int n_in,
                              void* d_out, int out_size)
{
    const float* x  = (const float*)d_in[0];
    const int*   bi = (const int*)  d_in[1];
    const float* gq = (const float*)d_in[2];
    const float* wq = (const float*)d_in[3];
    const float* bq = (const float*)d_in[4];
    const float* wk = (const float*)d_in[5];
    const float* bk = (const float*)d_in[6];
    const float* wv = (const float*)d_in[7];
    const float* bv = (const float*)d_in[8];
    const float* wo = (const float*)d_in[9];
    const float* bo = (const float*)d_in[10];
    const float* wp = (const float*)d_in[11];
    const float* bp = (const float*)d_in[12];
    float* out = (float*)d_out;

    void *pPooled, *pTmp;
    cudaGetSymbolAddress(&pPooled, g_pooled);
    cudaGetSymbolAddress(&pTmp, g_tmp);

    cudaFuncSetAttribute(attn_kernel, cudaFuncAttributeMaxDynamicSharedMemorySize, ATT_SMEM);
    cudaFuncSetAttribute(kv_gemm_kernel, cudaFuncAttributeMaxDynamicSharedMemorySize, GEMM_SMEM);

    convx_kernel<<<32768, 256>>>(x);
    convw_kernel<<<512, 256>>>(wk, wv);
    counts_kernel<<<1, NUM_G>>>(bi, bk, bv);

    kv_gemm_kernel<<<dim3(1024 / BN, N_NODES / BM), 256, GEMM_SMEM>>>();

    wqb_kernel<<<dim3(HEADS, 8), 512>>>(gq, wq);

    attn_kernel<<<dim3(NUM_G, HEADS), 256, ATT_SMEM>>>(bq);

    sgemm64_kernel<false><<<dim3(8, 8), 128>>>(
        (const float*)pPooled, wo, bo, (float*)pTmp, NUM_G, DIM, DIM);
    sgemm64_kernel<true><<<dim3(8, 8), 128>>>(
        (const float*)pTmp, wp, bp, out, NUM_G, DIM, DIM);
}